// round 3
// baseline (speedup 1.0000x reference)
#include <cuda_runtime.h>

// SimCLR supervised-contrastive loss, class-blocked.
// loss = mean_i( log(denom_i) ) - mean_i( dot_i / T ),
// denom_i = sum_{j: label_j==label_i, j!=i} exp(dot(out_i,out_j)/T)
// Only same-class pairs contribute -> counting-sort rows by label (7 classes),
// compute Gram only on class-diagonal blocks (7x less FLOP than full matrix).

#define NB 8192          // 2*BATCH rows
#define BHALF 4096
#define D 512
#define D4 (D/4)
#define NC 7
#define CHUNK 128
#define NCHUNK (NB/CHUNK)   // 64
#define TILE 128
#define NTILE (NB/TILE)     // 64
#define INV_T 2.0f          // 1/TEMPERATURE

// Scratch (allocation-free: __device__ globals)
__device__ float g_G[NB * D];            // gathered, class-sorted rows (16 MB)
__device__ int   g_perm[NB];
__device__ int   g_labp[NB];             // labels in permuted (sorted) order
__device__ int   g_chunkcnt[NCHUNK * NC];
__device__ int   g_chunkbase[NCHUNK * NC];
__device__ float g_denom[NB];            // per permuted row
__device__ float g_sums[2];              // [0] = sum log denom, [1] = sum dot(out1,out2)

// ---------------------------------------------------------------------------
__global__ void k_zero() {
    int i = blockIdx.x * blockDim.x + threadIdx.x;
    if (i < NB) g_denom[i] = 0.0f;
    if (i < 2)  g_sums[i]  = 0.0f;
}

// per-chunk label histogram (stable counting sort, step 1)
__global__ void k_hist(const int* __restrict__ labels) {
    __shared__ int s[NC];
    if (threadIdx.x < NC) s[threadIdx.x] = 0;
    __syncthreads();
    int i = blockIdx.x * CHUNK + threadIdx.x;
    atomicAdd(&s[labels[i]], 1);
    __syncthreads();
    if (threadIdx.x < NC) g_chunkcnt[blockIdx.x * NC + threadIdx.x] = s[threadIdx.x];
}

// serial scan over 64*7 counters (trivial)
__global__ void k_scan() {
    int tot[NC], off[NC];
    for (int c = 0; c < NC; c++) {
        int t = 0;
        for (int b = 0; b < NCHUNK; b++) t += g_chunkcnt[b * NC + c];
        tot[c] = t;
    }
    off[0] = 0;
    for (int c = 1; c < NC; c++) off[c] = off[c - 1] + tot[c - 1];
    for (int c = 0; c < NC; c++) {
        int run = off[c];
        for (int b = 0; b < NCHUNK; b++) {
            g_chunkbase[b * NC + c] = run;
            run += g_chunkcnt[b * NC + c];
        }
    }
}

// stable scatter: one serial thread per 128-element chunk (deterministic)
__global__ void k_scatter(const int* __restrict__ labels) {
    if (threadIdx.x != 0) return;
    int b = blockIdx.x;
    int cur[NC];
    for (int c = 0; c < NC; c++) cur[c] = g_chunkbase[b * NC + c];
    for (int t = 0; t < CHUNK; t++) {
        int i = b * CHUNK + t;
        int c = labels[i];
        int p = cur[c]++;
        g_perm[p] = i;
        g_labp[p] = c;
    }
}

// gather rows of `out` into class-sorted order
__global__ void k_gather(const float* __restrict__ out) {
    const float4* src = reinterpret_cast<const float4*>(out);
    float4* dst = reinterpret_cast<float4*>(g_G);
    int n = NB * D4;
    for (int i = blockIdx.x * blockDim.x + threadIdx.x; i < n;
         i += gridDim.x * blockDim.x) {
        int p = i >> 7;      // D4 == 128
        int q = i & 127;
        dst[i] = src[(size_t)g_perm[p] * D4 + q];
    }
}

// 128x128 Gram tile; skip tiles whose row/col class ranges don't intersect.
// Fused exp + mask + row-sum -> atomic into g_denom (permuted index space).
__global__ __launch_bounds__(256) void k_gemm() {
    const int r0 = blockIdx.y * TILE;
    const int c0 = blockIdx.x * TILE;
    {   // labels sorted ascending -> class-range intersection test
        int rlo = g_labp[r0], rhi = g_labp[r0 + TILE - 1];
        int clo = g_labp[c0], chi = g_labp[c0 + TILE - 1];
        if (rhi < clo || chi < rlo) return;
    }
    __shared__ float As[8][TILE];
    __shared__ float Bs[8][TILE];
    __shared__ float sden[TILE];
    __shared__ int   slr[TILE], slc[TILE];

    const int tid = threadIdx.x;
    if (tid < TILE) {
        slr[tid] = g_labp[r0 + tid];
        slc[tid] = g_labp[c0 + tid];
        sden[tid] = 0.0f;
    }
    const int tx = tid & 15;
    const int ty = tid >> 4;
    const int lrow = tid >> 1;          // 0..127
    const int lc4  = (tid & 1) << 2;    // 0 or 4

    const float4* G4 = reinterpret_cast<const float4*>(g_G);

    float acc[8][8];
#pragma unroll
    for (int mi = 0; mi < 8; mi++)
#pragma unroll
        for (int ni = 0; ni < 8; ni++) acc[mi][ni] = 0.0f;

    for (int kk = 0; kk < D; kk += 8) {
        float4 av = G4[(size_t)(r0 + lrow) * D4 + ((kk + lc4) >> 2)];
        float4 bv = G4[(size_t)(c0 + lrow) * D4 + ((kk + lc4) >> 2)];
        __syncthreads();
        As[lc4 + 0][lrow] = av.x; As[lc4 + 1][lrow] = av.y;
        As[lc4 + 2][lrow] = av.z; As[lc4 + 3][lrow] = av.w;
        Bs[lc4 + 0][lrow] = bv.x; Bs[lc4 + 1][lrow] = bv.y;
        Bs[lc4 + 2][lrow] = bv.z; Bs[lc4 + 3][lrow] = bv.w;
        __syncthreads();
#pragma unroll
        for (int k = 0; k < 8; k++) {
            float a[8], b[8];
#pragma unroll
            for (int mi = 0; mi < 8; mi++) a[mi] = As[k][ty + 16 * mi];
#pragma unroll
            for (int ni = 0; ni < 8; ni++) b[ni] = Bs[k][tx + 16 * ni];
#pragma unroll
            for (int mi = 0; mi < 8; mi++)
#pragma unroll
                for (int ni = 0; ni < 8; ni++)
                    acc[mi][ni] = fmaf(a[mi], b[ni], acc[mi][ni]);
        }
    }

    // epilogue: mask (same label, off-diagonal), exp, row-reduce
#pragma unroll
    for (int mi = 0; mi < 8; mi++) {
        int rr = ty + 16 * mi;
        int rl = slr[rr];
        float p = 0.0f;
#pragma unroll
        for (int ni = 0; ni < 8; ni++) {
            int cc = tx + 16 * ni;
            bool ok = (rl == slc[cc]) && ((r0 + rr) != (c0 + cc));
            float e = __expf(INV_T * acc[mi][ni]);
            p += ok ? e : 0.0f;
        }
        atomicAdd(&sden[rr], p);
    }
    __syncthreads();
    if (tid < TILE) atomicAdd(&g_denom[r0 + tid], sden[tid]);
}

// sum of dot(out_1[i], out_2[i]) over i<B
__global__ void k_pos(const float* __restrict__ o1, const float* __restrict__ o2) {
    __shared__ float red[256];
    const float4* a = reinterpret_cast<const float4*>(o1);
    const float4* b = reinterpret_cast<const float4*>(o2);
    float s = 0.0f;
    for (int i = blockIdx.x * blockDim.x + threadIdx.x; i < BHALF * D4;
         i += gridDim.x * blockDim.x) {
        float4 x = a[i], y = b[i];
        s += x.x * y.x + x.y * y.y + x.z * y.z + x.w * y.w;
    }
    red[threadIdx.x] = s;
    __syncthreads();
    for (int st = 128; st > 0; st >>= 1) {
        if (threadIdx.x < st) red[threadIdx.x] += red[threadIdx.x + st];
        __syncthreads();
    }
    if (threadIdx.x == 0) atomicAdd(&g_sums[1], red[0]);
}

// sum of log(denom)
__global__ void k_logdenom() {
    __shared__ float red[256];
    float s = 0.0f;
    for (int i = blockIdx.x * blockDim.x + threadIdx.x; i < NB;
         i += gridDim.x * blockDim.x) {
        s += logf(g_denom[i]);
    }
    red[threadIdx.x] = s;
    __syncthreads();
    for (int st = 128; st > 0; st >>= 1) {
        if (threadIdx.x < st) red[threadIdx.x] += red[threadIdx.x + st];
        __syncthreads();
    }
    if (threadIdx.x == 0) atomicAdd(&g_sums[0], red[0]);
}

// loss = sum_log/NB - (2 * sum_dot * INV_T) / NB  = sum_log/8192 - sum_dot/2048
__global__ void k_final(float* __restrict__ out) {
    out[0] = g_sums[0] / (float)NB - g_sums[1] * (2.0f * INV_T) / (float)NB;
}

extern "C" void kernel_launch(void* const* d_in, const int* in_sizes, int n_in,
                              void* d_out, int out_size) {
    const float* out_m  = (const float*)d_in[0];   // [2B, D]
    const float* out_1  = (const float*)d_in[1];   // [B, D]
    const float* out_2  = (const float*)d_in[2];   // [B, D]
    const int*   labels = (const int*)d_in[3];     // [2B]
    float* loss = (float*)d_out;

    k_zero<<<(NB + 255) / 256, 256>>>();
    k_hist<<<NCHUNK, CHUNK>>>(labels);
    k_scan<<<1, 1>>>();
    k_scatter<<<NCHUNK, 32>>>(labels);
    k_gather<<<2048, 256>>>(out_m);
    dim3 grid(NTILE, NTILE);
    k_gemm<<<grid, 256>>>();
    k_pos<<<256, 256>>>(out_1, out_2);
    k_logdenom<<<32, 256>>>();
    k_final<<<1, 1>>>(loss);
}

// round 7
// speedup vs baseline: 5.7205x; 5.7205x over previous
#include <cuda_runtime.h>
#include <cuda_bf16.h>
#include <cstdint>

// SimCLR supervised-contrastive loss, class-blocked, bf16 mma.sync GEMM.
// tcgen05 is unavailable: harness emits PTX .target sm_103 (no 'a'), which
// rejects all arch-specific (tcgen05/cta_group) instructions. mma.sync +
// ldmatrix are portable sm_80+ features and still give tensor-core rate.
//
// loss = mean(log denom) - mean(dot/T); only same-class pairs contribute ->
// counting-sort rows by label (7 classes), Gram only on class-diagonal blocks.
// Gram is symmetric: compute only tiles with c0 >= r0; off-diagonal tiles
// contribute their exp values to BOTH row sums and column sums.

#define NB 8192
#define BHALF 4096
#define D 512
#define D4 (D/4)
#define NC 7
#define CHUNK 128
#define NCHUNK (NB/CHUNK)
#define TILE 128
#define NTILE (NB/TILE)
#define INV_T 2.0f

// ---- scratch (__device__ globals; no allocation) ----
__device__ __nv_bfloat16 g_Gh[NB * D];   // class-sorted rows, bf16 (8 MB)
__device__ int   g_perm[NB];
__device__ int   g_labp[NB];
__device__ int   g_chunkcnt[NCHUNK * NC];
__device__ int   g_chunkbase[NCHUNK * NC];
__device__ float g_denom[NB];
__device__ float g_sums[2];

// ---------------------------------------------------------------------------
__global__ void k_zero() {
    int i = blockIdx.x * blockDim.x + threadIdx.x;
    if (i < NB) g_denom[i] = 0.0f;
    if (i < 2)  g_sums[i]  = 0.0f;
}

__global__ void k_hist(const int* __restrict__ labels) {
    __shared__ int s[NC];
    if (threadIdx.x < NC) s[threadIdx.x] = 0;
    __syncthreads();
    atomicAdd(&s[labels[blockIdx.x * CHUNK + threadIdx.x]], 1);
    __syncthreads();
    if (threadIdx.x < NC) g_chunkcnt[blockIdx.x * NC + threadIdx.x] = s[threadIdx.x];
}

__global__ void k_scan() {
    int tot[NC], off[NC];
    for (int c = 0; c < NC; c++) {
        int t = 0;
        for (int b = 0; b < NCHUNK; b++) t += g_chunkcnt[b * NC + c];
        tot[c] = t;
    }
    off[0] = 0;
    for (int c = 1; c < NC; c++) off[c] = off[c - 1] + tot[c - 1];
    for (int c = 0; c < NC; c++) {
        int run = off[c];
        for (int b = 0; b < NCHUNK; b++) {
            g_chunkbase[b * NC + c] = run;
            run += g_chunkcnt[b * NC + c];
        }
    }
}

// parallel stable scatter: rank = # earlier same-label entries in chunk
__global__ void k_scatter(const int* __restrict__ labels) {
    __shared__ int sl[CHUNK];
    int b = blockIdx.x, t = threadIdx.x;
    sl[t] = labels[b * CHUNK + t];
    __syncthreads();
    int c = sl[t], rank = 0;
    for (int s = 0; s < t; s++) rank += (sl[s] == c);
    int p = g_chunkbase[b * NC + c] + rank;
    g_perm[p] = b * CHUNK + t;
    g_labp[p] = c;
}

// gather rows of `out` into class-sorted order, converting to bf16
__global__ void k_gather(const float* __restrict__ out) {
    int n = NB * D / 8;
    for (int i = blockIdx.x * blockDim.x + threadIdx.x; i < n;
         i += gridDim.x * blockDim.x) {
        int p = i >> 6;
        int q = i & 63;
        const float4* s = reinterpret_cast<const float4*>(out + (size_t)g_perm[p] * D) + q * 2;
        float4 a = s[0], b = s[1];
        __nv_bfloat162 h0 = __floats2bfloat162_rn(a.x, a.y);
        __nv_bfloat162 h1 = __floats2bfloat162_rn(a.z, a.w);
        __nv_bfloat162 h2 = __floats2bfloat162_rn(b.x, b.y);
        __nv_bfloat162 h3 = __floats2bfloat162_rn(b.z, b.w);
        uint4 o;
        o.x = *reinterpret_cast<uint32_t*>(&h0);
        o.y = *reinterpret_cast<uint32_t*>(&h1);
        o.z = *reinterpret_cast<uint32_t*>(&h2);
        o.w = *reinterpret_cast<uint32_t*>(&h3);
        reinterpret_cast<uint4*>(g_Gh)[i] = o;
    }
}

// ---- mma.sync helpers ----
__device__ __forceinline__ uint32_t smem_u32(const void* p) {
    uint32_t a;
    asm("{ .reg .u64 t; cvta.to.shared.u64 t, %1; cvt.u32.u64 %0, t; }" : "=r"(a) : "l"(p));
    return a;
}
__device__ __forceinline__ void ldsm_x4(uint32_t* r, uint32_t addr) {
    asm volatile("ldmatrix.sync.aligned.m8n8.x4.shared.b16 {%0,%1,%2,%3}, [%4];"
                 : "=r"(r[0]), "=r"(r[1]), "=r"(r[2]), "=r"(r[3]) : "r"(addr));
}
__device__ __forceinline__ void mma16816(float* d, const uint32_t* a,
                                         uint32_t b0, uint32_t b1) {
    asm volatile(
        "mma.sync.aligned.m16n8k16.row.col.f32.bf16.bf16.f32 "
        "{%0,%1,%2,%3}, {%4,%5,%6,%7}, {%8,%9}, {%0,%1,%2,%3};"
        : "+f"(d[0]), "+f"(d[1]), "+f"(d[2]), "+f"(d[3])
        : "r"(a[0]), "r"(a[1]), "r"(a[2]), "r"(a[3]), "r"(b0), "r"(b1));
}
// smem byte offset for (row, 16B-chunk c) of a 128x32 bf16 tile, XOR swizzle:
// 8 consecutive rows hit 8 distinct 16B segments mod 128B -> conflict-free
// for both uint4 stores and ldmatrix row fetches.
__device__ __forceinline__ uint32_t sw(int row, int c16) {
    return (uint32_t)(row * 64 + ((c16 ^ ((row >> 1) & 3)) << 4));
}

#define BK 32
#define NKT (D / BK)   // 16 outer k-iterations

__global__ void __launch_bounds__(256, 2) k_gemm_mma() {
    const int r0 = blockIdx.y * TILE;
    const int c0 = blockIdx.x * TILE;
    if (c0 < r0) return;   // symmetry: only upper-triangular tile blocks
    {   // class-range intersection (labels sorted ascending)
        int rlo = g_labp[r0], rhi = g_labp[r0 + TILE - 1];
        int clo = g_labp[c0], chi = g_labp[c0 + TILE - 1];
        if (rhi < clo || chi < rlo) return;
    }
    __shared__ __align__(16) char As[2][8192];
    __shared__ __align__(16) char Bs[2][8192];
    __shared__ float sdenR[TILE];
    __shared__ float sdenC[TILE];
    __shared__ int   slr[TILE], slc[TILE];

    const int tid = threadIdx.x;
    const int wid = tid >> 5, lane = tid & 31;
    const int wm = wid >> 2, wn = wid & 3;        // warp tile: 64x32 at (wm*64, wn*32)
    const bool offdiag = (c0 != r0);

    if (tid < TILE) {
        slr[tid] = g_labp[r0 + tid];
        slc[tid] = g_labp[c0 + tid];
        sdenR[tid] = 0.0f;
        sdenC[tid] = 0.0f;
    }

    const uint4* src = reinterpret_cast<const uint4*>(g_Gh);   // 64 uint4 per row

    // loader indices: thread covers A/B uint4 positions p0, p1 of 512
    const int p0 = tid, p1 = tid + 256;
    const int p0r = p0 >> 2, p0c = p0 & 3;
    const int p1r = p1 >> 2, p1c = p1 & 3;

    uint4 ra0, ra1, rb0, rb1;
    // load k-chunk 0
    ra0 = src[(size_t)(r0 + p0r) * 64 + p0c];
    ra1 = src[(size_t)(r0 + p1r) * 64 + p1c];
    rb0 = src[(size_t)(c0 + p0r) * 64 + p0c];
    rb1 = src[(size_t)(c0 + p1r) * 64 + p1c];
    *reinterpret_cast<uint4*>(As[0] + sw(p0r, p0c)) = ra0;
    *reinterpret_cast<uint4*>(As[0] + sw(p1r, p1c)) = ra1;
    *reinterpret_cast<uint4*>(Bs[0] + sw(p0r, p0c)) = rb0;
    *reinterpret_cast<uint4*>(Bs[0] + sw(p1r, p1c)) = rb1;
    __syncthreads();

    const uint32_t sA0 = smem_u32(As[0]), sB0 = smem_u32(Bs[0]);
    const int g = lane >> 3, r8 = lane & 7;
    const int row_off = ((g & 1) << 3) + r8;      // ldmatrix row within 16-block
    const int cch = g >> 1;                       // ldmatrix k-chunk select

    float acc[4][4][4];
#pragma unroll
    for (int mf = 0; mf < 4; mf++)
#pragma unroll
        for (int nf = 0; nf < 4; nf++)
#pragma unroll
            for (int e = 0; e < 4; e++) acc[mf][nf][e] = 0.0f;

    int buf = 0;
    for (int t = 0; t < NKT; t++) {
        if (t < NKT - 1) {
            int kb = (t + 1) * 4;
            ra0 = src[(size_t)(r0 + p0r) * 64 + kb + p0c];
            ra1 = src[(size_t)(r0 + p1r) * 64 + kb + p1c];
            rb0 = src[(size_t)(c0 + p0r) * 64 + kb + p0c];
            rb1 = src[(size_t)(c0 + p1r) * 64 + kb + p1c];
        }
        const uint32_t aA = sA0 + buf * 8192;
        const uint32_t bB = sB0 + buf * 8192;
#pragma unroll
        for (int kc = 0; kc < 2; kc++) {
            uint32_t amat[4][4], bmat[2][4];
#pragma unroll
            for (int mf = 0; mf < 4; mf++)
                ldsm_x4(amat[mf], aA + sw(wm * 64 + mf * 16 + row_off, kc * 2 + cch));
#pragma unroll
            for (int nb = 0; nb < 2; nb++)
                ldsm_x4(bmat[nb], bB + sw(wn * 32 + nb * 16 + row_off, kc * 2 + cch));
#pragma unroll
            for (int mf = 0; mf < 4; mf++)
#pragma unroll
                for (int nf = 0; nf < 4; nf++)
                    mma16816(acc[mf][nf], amat[mf],
                             bmat[nf >> 1][nf & 1], bmat[nf >> 1][2 + (nf & 1)]);
        }
        __syncthreads();
        if (t < NKT - 1) {
            int nb = buf ^ 1;
            *reinterpret_cast<uint4*>(As[nb] + sw(p0r, p0c)) = ra0;
            *reinterpret_cast<uint4*>(As[nb] + sw(p1r, p1c)) = ra1;
            *reinterpret_cast<uint4*>(Bs[nb] + sw(p0r, p0c)) = rb0;
            *reinterpret_cast<uint4*>(Bs[nb] + sw(p1r, p1c)) = rb1;
            buf = nb;
            __syncthreads();
        }
    }

    // ---- epilogue: mask + exp; row sums always, col sums if offdiag tile ----
    const int qr = lane >> 2, qc = lane & 3;
    float colsum[4][2];
#pragma unroll
    for (int nf = 0; nf < 4; nf++) { colsum[nf][0] = 0.0f; colsum[nf][1] = 0.0f; }

#pragma unroll
    for (int mf = 0; mf < 4; mf++) {
#pragma unroll
        for (int h = 0; h < 2; h++) {
            const int r = wm * 64 + mf * 16 + h * 8 + qr;
            const int rl = slr[r];
            float rs = 0.0f;
#pragma unroll
            for (int nf = 0; nf < 4; nf++) {
#pragma unroll
                for (int e = 0; e < 2; e++) {
                    const int c = wn * 32 + nf * 8 + qc * 2 + e;
                    const float v = acc[mf][nf][h * 2 + e];
                    bool ok = (rl == slc[c]) && ((r0 + r) != (c0 + c));
                    float ex = ok ? __expf(INV_T * v) : 0.0f;
                    rs += ex;
                    colsum[nf][e] += ex;
                }
            }
            rs += __shfl_xor_sync(0xffffffffu, rs, 1);
            rs += __shfl_xor_sync(0xffffffffu, rs, 2);
            if (qc == 0) atomicAdd(&sdenR[r], rs);
        }
    }
    if (offdiag) {
#pragma unroll
        for (int nf = 0; nf < 4; nf++) {
#pragma unroll
            for (int e = 0; e < 2; e++) {
                float cs = colsum[nf][e];
                cs += __shfl_xor_sync(0xffffffffu, cs, 4);
                cs += __shfl_xor_sync(0xffffffffu, cs, 8);
                cs += __shfl_xor_sync(0xffffffffu, cs, 16);
                if (qr == 0) {
                    const int c = wn * 32 + nf * 8 + qc * 2 + e;
                    atomicAdd(&sdenC[c], cs);
                }
            }
        }
    }
    __syncthreads();
    if (tid < TILE) {
        atomicAdd(&g_denom[r0 + tid], sdenR[tid]);
        if (offdiag) atomicAdd(&g_denom[c0 + tid], sdenC[tid]);
    }
}

// sum of dot(out_1[i], out_2[i])
__global__ void k_pos(const float* __restrict__ o1, const float* __restrict__ o2) {
    __shared__ float red[256];
    const float4* a = reinterpret_cast<const float4*>(o1);
    const float4* b = reinterpret_cast<const float4*>(o2);
    float s = 0.0f;
    for (int i = blockIdx.x * blockDim.x + threadIdx.x; i < BHALF * D4;
         i += gridDim.x * blockDim.x) {
        float4 x = a[i], y = b[i];
        s += x.x * y.x + x.y * y.y + x.z * y.z + x.w * y.w;
    }
    red[threadIdx.x] = s;
    __syncthreads();
    for (int st = 128; st > 0; st >>= 1) {
        if (threadIdx.x < st) red[threadIdx.x] += red[threadIdx.x + st];
        __syncthreads();
    }
    if (threadIdx.x == 0) atomicAdd(&g_sums[1], red[0]);
}

__global__ void k_logdenom() {
    __shared__ float red[256];
    float s = 0.0f;
    for (int i = blockIdx.x * blockDim.x + threadIdx.x; i < NB;
         i += gridDim.x * blockDim.x)
        s += logf(g_denom[i]);
    red[threadIdx.x] = s;
    __syncthreads();
    for (int st = 128; st > 0; st >>= 1) {
        if (threadIdx.x < st) red[threadIdx.x] += red[threadIdx.x + st];
        __syncthreads();
    }
    if (threadIdx.x == 0) atomicAdd(&g_sums[0], red[0]);
}

__global__ void k_final(float* __restrict__ out) {
    out[0] = g_sums[0] / (float)NB - g_sums[1] * (2.0f * INV_T) / (float)NB;
}

extern "C" void kernel_launch(void* const* d_in, const int* in_sizes, int n_in,
                              void* d_out, int out_size) {
    const float* out_m  = (const float*)d_in[0];   // [2B, D]
    const float* out_1  = (const float*)d_in[1];   // [B, D]
    const float* out_2  = (const float*)d_in[2];   // [B, D]
    const int*   labels = (const int*)d_in[3];     // [2B]
    float* loss = (float*)d_out;

    k_zero<<<(NB + 255) / 256, 256>>>();
    k_hist<<<NCHUNK, CHUNK>>>(labels);
    k_scan<<<1, 1>>>();
    k_scatter<<<NCHUNK, CHUNK>>>(labels);
    k_gather<<<1024, 256>>>(out_m);
    dim3 grid(NTILE, NTILE);
    k_gemm_mma<<<grid, 256>>>();
    k_pos<<<256, 256>>>(out_1, out_2);
    k_logdenom<<<32, 256>>>();
    k_final<<<1, 1>>>(loss);
}

// round 10
// speedup vs baseline: 6.3873x; 1.1166x over previous
#include <cuda_runtime.h>
#include <cuda_bf16.h>
#include <cstdint>

// SimCLR supervised-contrastive loss, class-blocked, bf16 mma.sync GEMM.
// (tcgen05 unavailable: harness emits PTX .target sm_103 without 'a'.)
// Pipeline (4 launches): k_sort (fused hist/scan/scatter/zero, 1 block) ->
// k_gp (gather-to-bf16 + positive-pair reduction, fused) ->
// k_gemm_mma (class-blocked symmetric Gram, cp.async 3-stage, BK=64) ->
// k_fin (log-denom reduce + final scalar).

#define NB 8192
#define BHALF 4096
#define D 512
#define D4 (D/4)
#define NC 7
#define TILE 128
#define NTILE (NB/TILE)
#define INV_T 2.0f

// ---- scratch (__device__ globals; no allocation) ----
__device__ __nv_bfloat16 g_Gh[NB * D];   // class-sorted rows, bf16 (8 MB)
__device__ int   g_perm[NB];
__device__ int   g_labp[NB];
__device__ float g_denom[NB];
__device__ float g_sums[2];

// ---------------------------------------------------------------------------
// k_sort: one block, 1024 threads. Stable counting sort of 8192 labels into
// 7 classes via warp-shuffle scans; also zeroes g_denom / g_sums.
__global__ __launch_bounds__(1024) void k_sort(const int* __restrict__ labels) {
    __shared__ int swtot[NC][32];
    __shared__ int swex[NC][32];
    __shared__ int sctot[NC];
    __shared__ int sbase[NC];
    const int t = threadIdx.x, lane = t & 31, wid = t >> 5;

    int lab[8];
    int cnt[NC];
#pragma unroll
    for (int c = 0; c < NC; c++) cnt[c] = 0;
#pragma unroll
    for (int j = 0; j < 8; j++) {
        lab[j] = labels[t * 8 + j];
#pragma unroll
        for (int c = 0; c < NC; c++) cnt[c] += (lab[j] == c);
    }
    // warp-inclusive scan per class
    int inc[NC];
#pragma unroll
    for (int c = 0; c < NC; c++) {
        int v = cnt[c];
#pragma unroll
        for (int off = 1; off < 32; off <<= 1) {
            int u = __shfl_up_sync(0xffffffffu, v, off);
            if (lane >= off) v += u;
        }
        inc[c] = v;
        if (lane == 31) swtot[c][wid] = v;
    }
    // zero scratch while scan data settles
#pragma unroll
    for (int j = 0; j < 8; j++) g_denom[t * 8 + j] = 0.0f;
    if (t < 2) g_sums[t] = 0.0f;
    __syncthreads();
    // cross-warp scan: warp c scans class c over the 32 warp totals
    if (wid < NC) {
        int v = swtot[wid][lane];
        int orig = v;
#pragma unroll
        for (int off = 1; off < 32; off <<= 1) {
            int u = __shfl_up_sync(0xffffffffu, v, off);
            if (lane >= off) v += u;
        }
        swex[wid][lane] = v - orig;
        if (lane == 31) sctot[wid] = v;
    }
    __syncthreads();
    if (t == 0) {
        int run = 0;
#pragma unroll
        for (int c = 0; c < NC; c++) { sbase[c] = run; run += sctot[c]; }
    }
    __syncthreads();
    int off_[NC];
#pragma unroll
    for (int c = 0; c < NC; c++)
        off_[c] = sbase[c] + swex[c][wid] + inc[c] - cnt[c];
    // stable replay (thread covers contiguous elements, threads ordered)
#pragma unroll
    for (int j = 0; j < 8; j++) {
#pragma unroll
        for (int c = 0; c < NC; c++) {
            if (lab[j] == c) {
                int p = off_[c]++;
                g_perm[p] = t * 8 + j;
                g_labp[p] = c;
            }
        }
    }
}

// ---------------------------------------------------------------------------
// k_gp: blocks [0,1024) gather rows of `out` into class-sorted bf16 order;
// blocks [1024,1280) compute sum of dot(out_1[i], out_2[i]) -> g_sums[1].
#define GPB 1024
#define POSB 256
__global__ void k_gp(const float* __restrict__ outm,
                     const float* __restrict__ o1,
                     const float* __restrict__ o2) {
    const int b = blockIdx.x, tid = threadIdx.x;
    if (b < GPB) {
        const int n = NB * D / 8;
        for (int i = b * 256 + tid; i < n; i += GPB * 256) {
            int p = i >> 6;
            int q = i & 63;
            const float4* s =
                reinterpret_cast<const float4*>(outm + (size_t)g_perm[p] * D) + q * 2;
            float4 a = s[0], bb = s[1];
            __nv_bfloat162 h0 = __floats2bfloat162_rn(a.x, a.y);
            __nv_bfloat162 h1 = __floats2bfloat162_rn(a.z, a.w);
            __nv_bfloat162 h2 = __floats2bfloat162_rn(bb.x, bb.y);
            __nv_bfloat162 h3 = __floats2bfloat162_rn(bb.z, bb.w);
            uint4 o;
            o.x = *reinterpret_cast<uint32_t*>(&h0);
            o.y = *reinterpret_cast<uint32_t*>(&h1);
            o.z = *reinterpret_cast<uint32_t*>(&h2);
            o.w = *reinterpret_cast<uint32_t*>(&h3);
            reinterpret_cast<uint4*>(g_Gh)[i] = o;
        }
    } else {
        __shared__ float red[256];
        const float4* a = reinterpret_cast<const float4*>(o1);
        const float4* v = reinterpret_cast<const float4*>(o2);
        float s = 0.0f;
        for (int i = (b - GPB) * 256 + tid; i < BHALF * D4; i += POSB * 256) {
            float4 x = a[i], y = v[i];
            s += x.x * y.x + x.y * y.y + x.z * y.z + x.w * y.w;
        }
        red[tid] = s;
        __syncthreads();
        for (int st = 128; st > 0; st >>= 1) {
            if (tid < st) red[tid] += red[tid + st];
            __syncthreads();
        }
        if (tid == 0) atomicAdd(&g_sums[1], red[0]);
    }
}

// ---------------------------------------------------------------------------
// mma.sync helpers
__device__ __forceinline__ uint32_t smem_u32(const void* p) {
    uint32_t a;
    asm("{ .reg .u64 t; cvta.to.shared.u64 t, %1; cvt.u32.u64 %0, t; }" : "=r"(a) : "l"(p));
    return a;
}
__device__ __forceinline__ void ldsm_x4(uint32_t* r, uint32_t addr) {
    asm volatile("ldmatrix.sync.aligned.m8n8.x4.shared.b16 {%0,%1,%2,%3}, [%4];"
                 : "=r"(r[0]), "=r"(r[1]), "=r"(r[2]), "=r"(r[3]) : "r"(addr));
}
__device__ __forceinline__ void mma16816(float* d, const uint32_t* a,
                                         uint32_t b0, uint32_t b1) {
    asm volatile(
        "mma.sync.aligned.m16n8k16.row.col.f32.bf16.bf16.f32 "
        "{%0,%1,%2,%3}, {%4,%5,%6,%7}, {%8,%9}, {%0,%1,%2,%3};"
        : "+f"(d[0]), "+f"(d[1]), "+f"(d[2]), "+f"(d[3])
        : "r"(a[0]), "r"(a[1]), "r"(a[2]), "r"(a[3]), "r"(b0), "r"(b1));
}
// 128x64-bf16 tile (128B rows). XOR swizzle: conflict-free for cp.async 16B
// stores (8 distinct chunks per row-octet) and ldmatrix row fetches.
__device__ __forceinline__ uint32_t sw64(int row, int c16) {
    return (uint32_t)(row * 128 + ((c16 ^ (row & 7)) << 4));
}

#define BK 64
#define NKT (D / BK)          // 8
#define STAGE_BYTES 32768     // A 16KB + B 16KB per stage
#define NSTAGE 3

__global__ void __launch_bounds__(256, 2) k_gemm_mma() {
    const int r0 = blockIdx.y * TILE;
    const int c0 = blockIdx.x * TILE;
    if (c0 < r0) return;   // symmetry: upper-triangular tile blocks only
    {   // class-range intersection (labels sorted ascending)
        int rlo = g_labp[r0], rhi = g_labp[r0 + TILE - 1];
        int clo = g_labp[c0], chi = g_labp[c0 + TILE - 1];
        if (rhi < clo || chi < rlo) return;
    }
    extern __shared__ char dsm[];
    __shared__ float sdenR[TILE];
    __shared__ float sdenC[TILE];
    __shared__ int   slr[TILE], slc[TILE];

    const int tid = threadIdx.x;
    const int wid = tid >> 5, lane = tid & 31;
    const int wm = wid >> 2, wn = wid & 3;        // warp tile 64x32
    const bool offdiag = (c0 != r0);

    if (tid < TILE) {
        slr[tid] = g_labp[r0 + tid];
        slc[tid] = g_labp[c0 + tid];
        sdenR[tid] = 0.0f;
        sdenC[tid] = 0.0f;
    }

    const uint4* src = reinterpret_cast<const uint4*>(g_Gh);   // 64 uint4/row
    const uint32_t dyn = smem_u32(dsm);

    auto issue = [&](int t, int st) {
        const uint32_t sa = dyn + st * STAGE_BYTES;
#pragma unroll
        for (int j = 0; j < 4; j++) {
            int p = j * 256 + tid;          // coalesced: lane-consecutive 16B
            int row = p >> 3, c16 = p & 7;
            const uint4* gA = src + (size_t)(r0 + row) * 64 + t * 8 + c16;
            const uint4* gB = src + (size_t)(c0 + row) * 64 + t * 8 + c16;
            uint32_t dA = sa + sw64(row, c16);
            uint32_t dB = sa + 16384 + sw64(row, c16);
            asm volatile("cp.async.cg.shared.global [%0], [%1], 16;\n\t"
                         "cp.async.cg.shared.global [%2], [%3], 16;"
                         :: "r"(dA), "l"(gA), "r"(dB), "l"(gB));
        }
        asm volatile("cp.async.commit_group;" ::: "memory");
    };

    issue(0, 0);
    issue(1, 1);

    const int g = lane >> 3, r8 = lane & 7;
    const int row_off = ((g & 1) << 3) + r8;
    const int cch = g >> 1;

    float acc[4][4][4];
#pragma unroll
    for (int mf = 0; mf < 4; mf++)
#pragma unroll
        for (int nf = 0; nf < 4; nf++)
#pragma unroll
            for (int e = 0; e < 4; e++) acc[mf][nf][e] = 0.0f;

#pragma unroll
    for (int t = 0; t < NKT; t++) {
        // group t must be complete; group t+1 may remain in flight
        if (t < NKT - 1) asm volatile("cp.async.wait_group 1;" ::: "memory");
        else             asm volatile("cp.async.wait_group 0;" ::: "memory");
        __syncthreads();   // also protects stage (t+2)%3 from lagging readers
        if (t + 2 < NKT) issue(t + 2, (t + 2) % NSTAGE);

        const uint32_t sA = dyn + (t % NSTAGE) * STAGE_BYTES;
        const uint32_t sB = sA + 16384;
#pragma unroll
        for (int kc = 0; kc < 4; kc++) {
            uint32_t amat[4][4], bmat[2][4];
            const int c16 = kc * 2 + cch;
#pragma unroll
            for (int mf = 0; mf < 4; mf++)
                ldsm_x4(amat[mf], sA + sw64(wm * 64 + mf * 16 + row_off, c16));
#pragma unroll
            for (int nb = 0; nb < 2; nb++)
                ldsm_x4(bmat[nb], sB + sw64(wn * 32 + nb * 16 + row_off, c16));
#pragma unroll
            for (int mf = 0; mf < 4; mf++)
#pragma unroll
                for (int nf = 0; nf < 4; nf++)
                    mma16816(acc[mf][nf], amat[mf],
                             bmat[nf >> 1][nf & 1], bmat[nf >> 1][2 + (nf & 1)]);
        }
    }

    // ---- epilogue: mask + exp; row sums always, col sums if offdiag tile ----
    const int qr = lane >> 2, qc = lane & 3;
    float colsum[4][2];
#pragma unroll
    for (int nf = 0; nf < 4; nf++) { colsum[nf][0] = 0.0f; colsum[nf][1] = 0.0f; }

#pragma unroll
    for (int mf = 0; mf < 4; mf++) {
#pragma unroll
        for (int h = 0; h < 2; h++) {
            const int r = wm * 64 + mf * 16 + h * 8 + qr;
            const int rl = slr[r];
            float rs = 0.0f;
#pragma unroll
            for (int nf = 0; nf < 4; nf++) {
#pragma unroll
                for (int e = 0; e < 2; e++) {
                    const int c = wn * 32 + nf * 8 + qc * 2 + e;
                    const float v = acc[mf][nf][h * 2 + e];
                    bool ok = (rl == slc[c]) && ((r0 + r) != (c0 + c));
                    float ex = ok ? __expf(INV_T * v) : 0.0f;
                    rs += ex;
                    colsum[nf][e] += ex;
                }
            }
            rs += __shfl_xor_sync(0xffffffffu, rs, 1);
            rs += __shfl_xor_sync(0xffffffffu, rs, 2);
            if (qc == 0) atomicAdd(&sdenR[r], rs);
        }
    }
    if (offdiag) {
#pragma unroll
        for (int nf = 0; nf < 4; nf++) {
#pragma unroll
            for (int e = 0; e < 2; e++) {
                float cs = colsum[nf][e];
                cs += __shfl_xor_sync(0xffffffffu, cs, 4);
                cs += __shfl_xor_sync(0xffffffffu, cs, 8);
                cs += __shfl_xor_sync(0xffffffffu, cs, 16);
                if (qr == 0) {
                    const int c = wn * 32 + nf * 8 + qc * 2 + e;
                    atomicAdd(&sdenC[c], cs);
                }
            }
        }
    }
    __syncthreads();
    if (tid < TILE) {
        atomicAdd(&g_denom[r0 + tid], sdenR[tid]);
        if (offdiag) atomicAdd(&g_denom[c0 + tid], sdenC[tid]);
    }
}

// ---------------------------------------------------------------------------
// k_fin: sum log(denom) over 8192 rows + final scalar, one block.
__global__ __launch_bounds__(1024) void k_fin(float* __restrict__ out) {
    __shared__ float red[32];
    const int t = threadIdx.x, lane = t & 31, wid = t >> 5;
    float s = 0.0f;
#pragma unroll
    for (int j = 0; j < 8; j++) s += logf(g_denom[t * 8 + j]);
#pragma unroll
    for (int off = 16; off > 0; off >>= 1)
        s += __shfl_xor_sync(0xffffffffu, s, off);
    if (lane == 0) red[wid] = s;
    __syncthreads();
    if (wid == 0) {
        float v = red[lane];
#pragma unroll
        for (int off = 16; off > 0; off >>= 1)
            v += __shfl_xor_sync(0xffffffffu, v, off);
        if (lane == 0)
            out[0] = v / (float)NB - g_sums[1] * (2.0f * INV_T) / (float)NB;
    }
}

extern "C" void kernel_launch(void* const* d_in, const int* in_sizes, int n_in,
                              void* d_out, int out_size) {
    const float* out_m  = (const float*)d_in[0];   // [2B, D]
    const float* out_1  = (const float*)d_in[1];   // [B, D]
    const float* out_2  = (const float*)d_in[2];   // [B, D]
    const int*   labels = (const int*)d_in[3];     // [2B]
    float* loss = (float*)d_out;

    cudaFuncSetAttribute(k_gemm_mma, cudaFuncAttributeMaxDynamicSharedMemorySize,
                         NSTAGE * STAGE_BYTES);

    k_sort<<<1, 1024>>>(labels);
    k_gp<<<GPB + POSB, 256>>>(out_m, out_1, out_2);
    dim3 grid(NTILE, NTILE);
    k_gemm_mma<<<grid, 256, NSTAGE * STAGE_BYTES>>>();
    k_fin<<<1, 1024>>>(loss);
}

// round 11
// speedup vs baseline: 6.7983x; 1.0643x over previous
#include <cuda_runtime.h>
#include <cuda_bf16.h>
#include <cstdint>

// SimCLR supervised-contrastive loss, class-blocked, bf16 mma.sync GEMM.
// (tcgen05 unavailable: harness emits PTX .target sm_103 without 'a'.)
// Pipeline (4 launches):
//  k_sort  - fused hist/scan/scatter/zero + ACTIVE-TILE WORK LIST, 1 block
//  k_gp    - gather-to-bf16 (class-sorted) + positive-pair reduction
//  k_gemm  - dense 296-block grid striding over compacted tile list,
//            cp.async 3-stage, BK=64, symmetric (row+col sums per tile)
//  k_fin   - __logf denom reduce + final scalar

#define NB 8192
#define BHALF 4096
#define D 512
#define D4 (D/4)
#define NC 7
#define TILE 128
#define NTILE (NB/TILE)
#define NPAIR (NTILE*(NTILE+1)/2)   // 2080
#define INV_T 2.0f
#define GEMM_GRID 296

// ---- scratch (__device__ globals; no allocation) ----
__device__ __nv_bfloat16 g_Gh[NB * D];   // class-sorted rows, bf16 (8 MB)
__device__ int   g_perm[NB];
__device__ int   g_labp[NB];
__device__ float g_denom[NB];
__device__ float g_sums[2];
__device__ int   g_ntiles;
__device__ int   g_tiles[NPAIR];

// ---------------------------------------------------------------------------
// k_sort: one block, 1024 threads. Stable counting sort of 8192 labels into
// 7 classes via warp-shuffle scans; zeroes scratch; builds active-tile list.
__global__ __launch_bounds__(1024) void k_sort(const int* __restrict__ labels) {
    __shared__ int swtot[NC][32];
    __shared__ int swex[NC][32];
    __shared__ int sctot[NC];
    __shared__ int sbase[NC];
    __shared__ int scnt;
    const int t = threadIdx.x, lane = t & 31, wid = t >> 5;

    int lab[8];
    int cnt[NC];
#pragma unroll
    for (int c = 0; c < NC; c++) cnt[c] = 0;
#pragma unroll
    for (int j = 0; j < 8; j++) {
        lab[j] = labels[t * 8 + j];
#pragma unroll
        for (int c = 0; c < NC; c++) cnt[c] += (lab[j] == c);
    }
    // warp-inclusive scan per class
    int inc[NC];
#pragma unroll
    for (int c = 0; c < NC; c++) {
        int v = cnt[c];
#pragma unroll
        for (int off = 1; off < 32; off <<= 1) {
            int u = __shfl_up_sync(0xffffffffu, v, off);
            if (lane >= off) v += u;
        }
        inc[c] = v;
        if (lane == 31) swtot[c][wid] = v;
    }
#pragma unroll
    for (int j = 0; j < 8; j++) g_denom[t * 8 + j] = 0.0f;
    if (t < 2) g_sums[t] = 0.0f;
    if (t == 0) scnt = 0;
    __syncthreads();
    // cross-warp scan: warp c scans class c over the 32 warp totals
    if (wid < NC) {
        int v = swtot[wid][lane];
        int orig = v;
#pragma unroll
        for (int off = 1; off < 32; off <<= 1) {
            int u = __shfl_up_sync(0xffffffffu, v, off);
            if (lane >= off) v += u;
        }
        swex[wid][lane] = v - orig;
        if (lane == 31) sctot[wid] = v;
    }
    __syncthreads();
    if (t == 0) {
        int run = 0;
#pragma unroll
        for (int c = 0; c < NC; c++) { sbase[c] = run; run += sctot[c]; }
    }
    __syncthreads();
    int off_[NC];
#pragma unroll
    for (int c = 0; c < NC; c++)
        off_[c] = sbase[c] + swex[c][wid] + inc[c] - cnt[c];
    // stable replay (thread covers contiguous elements, threads ordered)
#pragma unroll
    for (int j = 0; j < 8; j++) {
#pragma unroll
        for (int c = 0; c < NC; c++) {
            if (lab[j] == c) {
                int p = off_[c]++;
                g_perm[p] = t * 8 + j;
                g_labp[p] = c;
            }
        }
    }
    __syncthreads();   // g_labp visible block-wide

    // build active-tile list over upper-triangular (i <= j) tile pairs
    for (int idx = t; idx < NPAIR; idx += 1024) {
        int i = 0, rem = idx;
        while (rem >= NTILE - i) { rem -= NTILE - i; i++; }
        int j = i + rem;
        int rlo = g_labp[i * TILE], rhi = g_labp[i * TILE + TILE - 1];
        int clo = g_labp[j * TILE], chi = g_labp[j * TILE + TILE - 1];
        if (!(rhi < clo || chi < rlo)) {
            int p = atomicAdd(&scnt, 1);
            g_tiles[p] = (i << 16) | j;
        }
    }
    __syncthreads();
    if (t == 0) g_ntiles = scnt;
}

// ---------------------------------------------------------------------------
// k_gp: blocks [0,1024) gather rows of `out` into class-sorted bf16 order;
// blocks [1024,1280) compute sum of dot(out_1[i], out_2[i]) -> g_sums[1].
#define GPB 1024
#define POSB 256
__global__ void k_gp(const float* __restrict__ outm,
                     const float* __restrict__ o1,
                     const float* __restrict__ o2) {
    const int b = blockIdx.x, tid = threadIdx.x;
    if (b < GPB) {
        const int n = NB * D / 8;
        for (int i = b * 256 + tid; i < n; i += GPB * 256) {
            int p = i >> 6;
            int q = i & 63;
            const float4* s =
                reinterpret_cast<const float4*>(outm + (size_t)g_perm[p] * D) + q * 2;
            float4 a = s[0], bb = s[1];
            __nv_bfloat162 h0 = __floats2bfloat162_rn(a.x, a.y);
            __nv_bfloat162 h1 = __floats2bfloat162_rn(a.z, a.w);
            __nv_bfloat162 h2 = __floats2bfloat162_rn(bb.x, bb.y);
            __nv_bfloat162 h3 = __floats2bfloat162_rn(bb.z, bb.w);
            uint4 o;
            o.x = *reinterpret_cast<uint32_t*>(&h0);
            o.y = *reinterpret_cast<uint32_t*>(&h1);
            o.z = *reinterpret_cast<uint32_t*>(&h2);
            o.w = *reinterpret_cast<uint32_t*>(&h3);
            reinterpret_cast<uint4*>(g_Gh)[i] = o;
        }
    } else {
        __shared__ float red[256];
        const float4* a = reinterpret_cast<const float4*>(o1);
        const float4* v = reinterpret_cast<const float4*>(o2);
        float s = 0.0f;
        for (int i = (b - GPB) * 256 + tid; i < BHALF * D4; i += POSB * 256) {
            float4 x = a[i], y = v[i];
            s += x.x * y.x + x.y * y.y + x.z * y.z + x.w * y.w;
        }
        red[tid] = s;
        __syncthreads();
        for (int st = 128; st > 0; st >>= 1) {
            if (tid < st) red[tid] += red[tid + st];
            __syncthreads();
        }
        if (tid == 0) atomicAdd(&g_sums[1], red[0]);
    }
}

// ---------------------------------------------------------------------------
// mma.sync helpers
__device__ __forceinline__ uint32_t smem_u32(const void* p) {
    uint32_t a;
    asm("{ .reg .u64 t; cvta.to.shared.u64 t, %1; cvt.u32.u64 %0, t; }" : "=r"(a) : "l"(p));
    return a;
}
__device__ __forceinline__ void ldsm_x4(uint32_t* r, uint32_t addr) {
    asm volatile("ldmatrix.sync.aligned.m8n8.x4.shared.b16 {%0,%1,%2,%3}, [%4];"
                 : "=r"(r[0]), "=r"(r[1]), "=r"(r[2]), "=r"(r[3]) : "r"(addr));
}
__device__ __forceinline__ void mma16816(float* d, const uint32_t* a,
                                         uint32_t b0, uint32_t b1) {
    asm volatile(
        "mma.sync.aligned.m16n8k16.row.col.f32.bf16.bf16.f32 "
        "{%0,%1,%2,%3}, {%4,%5,%6,%7}, {%8,%9}, {%0,%1,%2,%3};"
        : "+f"(d[0]), "+f"(d[1]), "+f"(d[2]), "+f"(d[3])
        : "r"(a[0]), "r"(a[1]), "r"(a[2]), "r"(a[3]), "r"(b0), "r"(b1));
}
// 128x64-bf16 tile (128B rows). XOR swizzle: conflict-free for cp.async 16B
// stores and ldmatrix row fetches.
__device__ __forceinline__ uint32_t sw64(int row, int c16) {
    return (uint32_t)(row * 128 + ((c16 ^ (row & 7)) << 4));
}

#define BK 64
#define NKT (D / BK)          // 8
#define STAGE_BYTES 32768     // A 16KB + B 16KB per stage
#define NSTAGE 3

__global__ void __launch_bounds__(256, 2) k_gemm_mma() {
    extern __shared__ char dsm[];
    __shared__ float sdenR[TILE];
    __shared__ float sdenC[TILE];
    __shared__ int   slr[TILE], slc[TILE];

    const int tid = threadIdx.x;
    const int wid = tid >> 5, lane = tid & 31;
    const int wm = wid >> 2, wn = wid & 3;        // warp tile 64x32
    const uint4* src = reinterpret_cast<const uint4*>(g_Gh);   // 64 uint4/row
    const uint32_t dyn = smem_u32(dsm);

    const int g = lane >> 3, r8 = lane & 7;
    const int row_off = ((g & 1) << 3) + r8;
    const int cch = g >> 1;
    const int qr = lane >> 2, qc = lane & 3;
    const int ntiles = g_ntiles;

    for (int w = blockIdx.x; w < ntiles; w += GEMM_GRID) {
        const int item = g_tiles[w];
        const int r0 = (item >> 16) * TILE;
        const int c0 = (item & 0xffff) * TILE;
        const bool offdiag = (c0 != r0);

        if (tid < TILE) {
            slr[tid] = g_labp[r0 + tid];
            slc[tid] = g_labp[c0 + tid];
            sdenR[tid] = 0.0f;
            sdenC[tid] = 0.0f;
        }

        auto issue = [&](int t, int st) {
            const uint32_t sa = dyn + st * STAGE_BYTES;
#pragma unroll
            for (int j = 0; j < 4; j++) {
                int p = j * 256 + tid;
                int row = p >> 3, c16 = p & 7;
                const uint4* gA = src + (size_t)(r0 + row) * 64 + t * 8 + c16;
                const uint4* gB = src + (size_t)(c0 + row) * 64 + t * 8 + c16;
                uint32_t dA = sa + sw64(row, c16);
                uint32_t dB = sa + 16384 + sw64(row, c16);
                asm volatile("cp.async.cg.shared.global [%0], [%1], 16;\n\t"
                             "cp.async.cg.shared.global [%2], [%3], 16;"
                             :: "r"(dA), "l"(gA), "r"(dB), "l"(gB));
            }
            asm volatile("cp.async.commit_group;" ::: "memory");
        };

        issue(0, 0);
        issue(1, 1);

        float acc[4][4][4];
#pragma unroll
        for (int mf = 0; mf < 4; mf++)
#pragma unroll
            for (int nf = 0; nf < 4; nf++)
#pragma unroll
                for (int e = 0; e < 4; e++) acc[mf][nf][e] = 0.0f;

#pragma unroll
        for (int t = 0; t < NKT; t++) {
            if (t < NKT - 1) asm volatile("cp.async.wait_group 1;" ::: "memory");
            else             asm volatile("cp.async.wait_group 0;" ::: "memory");
            __syncthreads();
            if (t + 2 < NKT) issue(t + 2, (t + 2) % NSTAGE);

            const uint32_t sA = dyn + (t % NSTAGE) * STAGE_BYTES;
            const uint32_t sB = sA + 16384;
#pragma unroll
            for (int kc = 0; kc < 4; kc++) {
                uint32_t amat[4][4], bmat[2][4];
                const int c16 = kc * 2 + cch;
#pragma unroll
                for (int mf = 0; mf < 4; mf++)
                    ldsm_x4(amat[mf], sA + sw64(wm * 64 + mf * 16 + row_off, c16));
#pragma unroll
                for (int nb = 0; nb < 2; nb++)
                    ldsm_x4(bmat[nb], sB + sw64(wn * 32 + nb * 16 + row_off, c16));
#pragma unroll
                for (int mf = 0; mf < 4; mf++)
#pragma unroll
                    for (int nf = 0; nf < 4; nf++)
                        mma16816(acc[mf][nf], amat[mf],
                                 bmat[nf >> 1][nf & 1], bmat[nf >> 1][2 + (nf & 1)]);
            }
        }

        // ---- epilogue: mask + exp; row sums always, col sums if offdiag ----
        float colsum[4][2];
#pragma unroll
        for (int nf = 0; nf < 4; nf++) { colsum[nf][0] = 0.0f; colsum[nf][1] = 0.0f; }

#pragma unroll
        for (int mf = 0; mf < 4; mf++) {
#pragma unroll
            for (int h = 0; h < 2; h++) {
                const int r = wm * 64 + mf * 16 + h * 8 + qr;
                const int rl = slr[r];
                float rs = 0.0f;
#pragma unroll
                for (int nf = 0; nf < 4; nf++) {
#pragma unroll
                    for (int e = 0; e < 2; e++) {
                        const int c = wn * 32 + nf * 8 + qc * 2 + e;
                        const float v = acc[mf][nf][h * 2 + e];
                        bool ok = (rl == slc[c]) && ((r0 + r) != (c0 + c));
                        float ex = ok ? __expf(INV_T * v) : 0.0f;
                        rs += ex;
                        colsum[nf][e] += ex;
                    }
                }
                rs += __shfl_xor_sync(0xffffffffu, rs, 1);
                rs += __shfl_xor_sync(0xffffffffu, rs, 2);
                if (qc == 0) atomicAdd(&sdenR[r], rs);
            }
        }
        if (offdiag) {
#pragma unroll
            for (int nf = 0; nf < 4; nf++) {
#pragma unroll
                for (int e = 0; e < 2; e++) {
                    float cs = colsum[nf][e];
                    cs += __shfl_xor_sync(0xffffffffu, cs, 4);
                    cs += __shfl_xor_sync(0xffffffffu, cs, 8);
                    cs += __shfl_xor_sync(0xffffffffu, cs, 16);
                    if (qr == 0) {
                        const int c = wn * 32 + nf * 8 + qc * 2 + e;
                        atomicAdd(&sdenC[c], cs);
                    }
                }
            }
        }
        __syncthreads();
        if (tid < TILE) {
            atomicAdd(&g_denom[r0 + tid], sdenR[tid]);
            if (offdiag) atomicAdd(&g_denom[c0 + tid], sdenC[tid]);
        }
        __syncthreads();   // protect sden/sl* reuse on next work item
    }
}

// ---------------------------------------------------------------------------
// k_fin: sum __logf(denom) over 8192 rows + final scalar, one block.
__global__ __launch_bounds__(1024) void k_fin(float* __restrict__ out) {
    __shared__ float red[32];
    const int t = threadIdx.x, lane = t & 31, wid = t >> 5;
    float s = 0.0f;
#pragma unroll
    for (int j = 0; j < 8; j++) s += __logf(g_denom[t * 8 + j]);
#pragma unroll
    for (int off = 16; off > 0; off >>= 1)
        s += __shfl_xor_sync(0xffffffffu, s, off);
    if (lane == 0) red[wid] = s;
    __syncthreads();
    if (wid == 0) {
        float v = red[lane];
#pragma unroll
        for (int off = 16; off > 0; off >>= 1)
            v += __shfl_xor_sync(0xffffffffu, v, off);
        if (lane == 0)
            out[0] = v / (float)NB - g_sums[1] * (2.0f * INV_T) / (float)NB;
    }
}

extern "C" void kernel_launch(void* const* d_in, const int* in_sizes, int n_in,
                              void* d_out, int out_size) {
    const float* out_m  = (const float*)d_in[0];   // [2B, D]
    const float* out_1  = (const float*)d_in[1];   // [B, D]
    const float* out_2  = (const float*)d_in[2];   // [B, D]
    const int*   labels = (const int*)d_in[3];     // [2B]
    float* loss = (float*)d_out;

    cudaFuncSetAttribute(k_gemm_mma, cudaFuncAttributeMaxDynamicSharedMemorySize,
                         NSTAGE * STAGE_BYTES);

    k_sort<<<1, 1024>>>(labels);
    k_gp<<<GPB + POSB, 256>>>(out_m, out_1, out_2);
    k_gemm_mma<<<GEMM_GRID, 256, NSTAGE * STAGE_BYTES>>>();
    k_fin<<<1, 1024>>>(loss);
}